// round 16
// baseline (speedup 1.0000x reference)
#include <cuda_runtime.h>
#include <stdint.h>

#define N_LEVELS 6
#define HASHMAP_SIZE (1u << 19)
#define HASH_MASK    (HASHMAP_SIZE - 1u)
#define SPHERE_R 500.0f

#define OCT_RES   512
#define NBINS     (OCT_RES * OCT_RES)      // 262144 bins per half
#define SCAN_CHUNK 2048
#define SCAN_BLOCKS (NBINS / SCAN_CHUNK)   // 128

#define N_RAYS_MAX 1048576

// per-half scratch (uint4 alignment for vector access); zero-init at load, scan re-zeroes
__device__ uint4    d_hist0[NBINS / 4];
__device__ uint4    d_hist1[NBINS / 4];
__device__ uint4    d_off0[NBINS / 4];
__device__ uint4    d_off1[NBINS / 4];
__device__ uint32_t d_bsum0[SCAN_BLOCKS];
__device__ uint32_t d_bsum1[SCAN_BLOCKS];
__device__ float4   d_sorted[N_RAYS_MAX];  // (cx,cy,cz, orig-as-bits), bin-sorted per half

// ---------------------------------------------------------------- helpers
__device__ __forceinline__ uint32_t expand2(uint32_t v)
{
    v &= 0xFFFFu;
    v = (v | (v << 8)) & 0x00FF00FFu;
    v = (v | (v << 4)) & 0x0F0F0F0Fu;
    v = (v | (v << 2)) & 0x33333333u;
    v = (v | (v << 1)) & 0x55555555u;
    return v;
}

__device__ __forceinline__ float3 ray_coords(const float* __restrict__ dirs,
                                             const float* __restrict__ origs, int i)
{
    const float dx = dirs[3 * i + 0], dy = dirs[3 * i + 1], dz = dirs[3 * i + 2];
    const float ox = origs[3 * i + 0], oy = origs[3 * i + 1], oz = origs[3 * i + 2];
    float b    = 2.0f * (ox * dx + oy * dy + oz * dz);
    float c    = (ox * ox + oy * oy + oz * oz) - SPHERE_R * SPHERE_R;
    float disc = b * b - 4.0f * c;
    float t    = 0.5f * (sqrtf(fmaxf(disc, 0.0f)) - b);
    const float inv2R = 1.0f / (2.0f * SPHERE_R);
    float3 r;
    r.x = fminf(fmaxf((ox + t * dx + SPHERE_R) * inv2R, 0.0f), 1.0f);
    r.y = fminf(fmaxf((oy + t * dy + SPHERE_R) * inv2R, 0.0f), 1.0f);
    r.z = fminf(fmaxf((oz + t * dz + SPHERE_R) * inv2R, 0.0f), 1.0f);
    return r;
}

__device__ __forceinline__ uint32_t oct_bin(float3 cc)
{
    float px = 2.0f * cc.x - 1.0f;
    float py = 2.0f * cc.y - 1.0f;
    float pz = 2.0f * cc.z - 1.0f;
    float inv = 1.0f / (fabsf(px) + fabsf(py) + fabsf(pz));
    float u = px * inv, v = py * inv;
    if (pz < 0.0f) {
        float uu = (1.0f - fabsf(v)) * copysignf(1.0f, u);
        float vv = (1.0f - fabsf(u)) * copysignf(1.0f, v);
        u = uu; v = vv;
    }
    uint32_t bu = min((uint32_t)((u * 0.5f + 0.5f) * (float)OCT_RES), (uint32_t)(OCT_RES - 1));
    uint32_t bv = min((uint32_t)((v * 0.5f + 0.5f) * (float)OCT_RES), (uint32_t)(OCT_RES - 1));
    return expand2(bu) | (expand2(bv) << 1);
}

__device__ __forceinline__ void stcs_f4(float4* p, float4 v)
{
    asm volatile("st.global.cs.v4.f32 [%0], {%1,%2,%3,%4};"
                 :: "l"(p), "f"(v.x), "f"(v.y), "f"(v.z), "f"(v.w) : "memory");
}
__device__ __forceinline__ float4 ldcs_f4(const float4* p)
{
    float4 v;
    asm volatile("ld.global.cs.v4.f32 {%0,%1,%2,%3}, [%4];"
                 : "=f"(v.x), "=f"(v.y), "=f"(v.z), "=f"(v.w) : "l"(p));
    return v;
}

// ---------------------------------------------------------------- stage: histogram
__device__ __forceinline__ void dev_hist(const float* __restrict__ dirs,
                                         const float* __restrict__ origs,
                                         int rbase, int cnt, uint32_t* hist, int blk)
{
    int i = blk * 256 + threadIdx.x;
    if (i >= cnt) return;
    uint32_t bin = oct_bin(ray_coords(dirs, origs, rbase + i));
    atomicAdd(&hist[bin], 1u);
}

// ---------------------------------------------------------------- stage: per-chunk scan (256t, 8 bins/thread) + re-zero
__device__ __forceinline__ void dev_scan(uint32_t* hist, uint32_t* offsets,
                                         uint32_t* bsum, int blk)
{
    __shared__ uint32_t wsum[8];
    const int tid = threadIdx.x;
    const int lane = tid & 31, wid = tid >> 5;
    const int base = blk * SCAN_CHUNK + tid * 8;
    uint4 e0 = *reinterpret_cast<uint4*>(hist + base);
    uint4 e1 = *reinterpret_cast<uint4*>(hist + base + 4);
    *reinterpret_cast<uint4*>(hist + base)     = make_uint4(0u, 0u, 0u, 0u);
    *reinterpret_cast<uint4*>(hist + base + 4) = make_uint4(0u, 0u, 0u, 0u);
    uint32_t s = e0.x + e0.y + e0.z + e0.w + e1.x + e1.y + e1.z + e1.w;
    uint32_t x = s;
#pragma unroll
    for (int d = 1; d < 32; d <<= 1) {
        uint32_t y = __shfl_up_sync(0xffffffffu, x, d);
        if (lane >= d) x += y;
    }
    if (lane == 31) wsum[wid] = x;
    __syncthreads();
    uint32_t add = 0;
#pragma unroll
    for (int k = 0; k < 8; ++k)
        if (k < wid) add += wsum[k];
    uint32_t o = add + (x - s);   // exclusive prefix of this thread's 8 bins
    uint4 w;
    w.x = o;             w.y = w.x + e0.x;  w.z = w.y + e0.y;  w.w = w.z + e0.z;
    *reinterpret_cast<uint4*>(offsets + base) = w;
    o = w.w + e0.w;
    w.x = o;             w.y = w.x + e1.x;  w.z = w.y + e1.y;  w.w = w.z + e1.z;
    *reinterpret_cast<uint4*>(offsets + base + 4) = w;
    if (tid == 255) bsum[blk] = add + x;   // block (chunk) total
}

// ---------------------------------------------------------------- stage: scatter sorted records
__device__ __forceinline__ void dev_scatter(const float* __restrict__ dirs,
                                            const float* __restrict__ origs,
                                            int rbase, int cnt,
                                            uint32_t* offsets, const uint32_t* bsum,
                                            uint32_t sbase, int blk)
{
    __shared__ uint32_t s_base[SCAN_BLOCKS];
    __shared__ uint32_t s_w[4];
    const int tid = threadIdx.x;
    const int lane = tid & 31, wid = tid >> 5;

    if (wid < 4) {
        uint32_t v = __ldg(&bsum[wid * 32 + lane]);
        uint32_t x = v;
#pragma unroll
        for (int d = 1; d < 32; d <<= 1) {
            uint32_t y = __shfl_up_sync(0xffffffffu, x, d);
            if (lane >= d) x += y;
        }
        if (lane == 31) s_w[wid] = x;
        __syncthreads();
        uint32_t add = 0;
#pragma unroll
        for (int k = 0; k < 4; ++k)
            if (k < wid) add += s_w[k];
        s_base[wid * 32 + lane] = x - v + add;   // exclusive chunk base
    } else {
        __syncthreads();
    }
    __syncthreads();

    int i = blk * 256 + tid;
    if (i >= cnt) return;
    float3 cc = ray_coords(dirs, origs, rbase + i);
    uint32_t bin = oct_bin(cc);
    uint32_t pos = atomicAdd(&offsets[bin], 1u) + s_base[bin >> 11] + sbase;
    stcs_f4(&d_sorted[pos],
            make_float4(cc.x, cc.y, cc.z, __uint_as_float((uint32_t)(rbase + i))));
}

// ---------------------------------------------------------------- stage: encode
template<int L>
__device__ __forceinline__ void level_idx(float cx, float cy, float cz,
                                          uint32_t* idx, float3& w)
{
    const float scale = (float)((16 << L) - 1);
    float px = cx * scale + 0.5f;
    float py = cy * scale + 0.5f;
    float pz = cz * scale + 0.5f;
    float fx = floorf(px), fy = floorf(py), fz = floorf(pz);
    w.x = px - fx; w.y = py - fy; w.z = pz - fz;
    uint32_t gx = (uint32_t)fx, gy = (uint32_t)fy, gz = (uint32_t)fz;

    if (L < 3) {
        const uint32_t r  = 16u << L;
        const uint32_t rm = r - 1u;
        uint32_t x0 = gx,            x1 = min(gx + 1u, rm);
        uint32_t y0 = gy * r,        y1 = min(gy + 1u, rm) * r;
        uint32_t z0 = gz * r * r,    z1 = min(gz + 1u, rm) * r * r;
        idx[0] = x0 + y0 + z0; idx[1] = x1 + y0 + z0;
        idx[2] = x0 + y1 + z0; idx[3] = x1 + y1 + z0;
        idx[4] = x0 + y0 + z1; idx[5] = x1 + y0 + z1;
        idx[6] = x0 + y1 + z1; idx[7] = x1 + y1 + z1;
    } else {
        uint32_t hx0 = gx,               hx1 = gx + 1u;
        uint32_t hy0 = gy * 2654435761u, hy1 = hy0 + 2654435761u;
        uint32_t hz0 = gz * 805459861u,  hz1 = hz0 + 805459861u;
        idx[0] = (hx0 ^ hy0 ^ hz0) & HASH_MASK; idx[1] = (hx1 ^ hy0 ^ hz0) & HASH_MASK;
        idx[2] = (hx0 ^ hy1 ^ hz0) & HASH_MASK; idx[3] = (hx1 ^ hy1 ^ hz0) & HASH_MASK;
        idx[4] = (hx0 ^ hy0 ^ hz1) & HASH_MASK; idx[5] = (hx1 ^ hy0 ^ hz1) & HASH_MASK;
        idx[6] = (hx0 ^ hy1 ^ hz1) & HASH_MASK; idx[7] = (hx1 ^ hy1 ^ hz1) & HASH_MASK;
    }
}

__device__ __forceinline__ void load8(float4* f, const float4* tab, const uint32_t* idx)
{
#pragma unroll
    for (int k = 0; k < 8; ++k) f[k] = __ldg(tab + idx[k]);
}

__device__ __forceinline__ float4 blend8(const float4* f, float3 w)
{
    float ux = 1.0f - w.x, uy = 1.0f - w.y, uz = 1.0f - w.z;
    float w0 = ux * uy * uz, w1 = w.x * uy * uz;
    float w2 = ux * w.y * uz, w3 = w.x * w.y * uz;
    float w4 = ux * uy * w.z, w5 = w.x * uy * w.z;
    float w6 = ux * w.y * w.z, w7 = w.x * w.y * w.z;
    float4 a;
    a.x = f[0].x*w0 + f[1].x*w1 + f[2].x*w2 + f[3].x*w3 + f[4].x*w4 + f[5].x*w5 + f[6].x*w6 + f[7].x*w7;
    a.y = f[0].y*w0 + f[1].y*w1 + f[2].y*w2 + f[3].y*w3 + f[4].y*w4 + f[5].y*w5 + f[6].y*w6 + f[7].y*w7;
    a.z = f[0].z*w0 + f[1].z*w1 + f[2].z*w2 + f[3].z*w3 + f[4].z*w4 + f[5].z*w5 + f[6].z*w6 + f[7].z*w7;
    a.w = f[0].w*w0 + f[1].w*w1 + f[2].w*w2 + f[3].w*w3 + f[4].w*w4 + f[5].w*w5 + f[6].w*w6 + f[7].w*w7;
    return a;
}

__device__ __forceinline__ void dev_encode(const float* __restrict__ table,
                                           float4* __restrict__ out,
                                           uint32_t sbase, int cnt, int blk)
{
    __shared__ float sbuf[8][32][28];

    int jj = blk * 256 + threadIdx.x;
    const int lane = threadIdx.x & 31;
    const int w    = threadIdx.x >> 5;
    bool active = (jj < cnt);

    float4 c = ldcs_f4(&d_sorted[sbase + (active ? jj : 0)]);
    uint32_t orig = __float_as_uint(c.w);
    const float cx = c.x, cy = c.y, cz = c.z;

    const float4* tb = reinterpret_cast<const float4*>(table);
    float* srow = &sbuf[w][lane][0];

    uint32_t ia[8], ib[8];
    float3 wa, wb;
    float4 A[8], B[8];

    level_idx<5>(cx, cy, cz, ia, wa); load8(A, tb + 5u * HASHMAP_SIZE, ia);
    level_idx<4>(cx, cy, cz, ib, wb); load8(B, tb + 4u * HASHMAP_SIZE, ib);
    *reinterpret_cast<float4*>(srow + 5 * 4) = blend8(A, wa);
    level_idx<3>(cx, cy, cz, ia, wa); load8(A, tb + 3u * HASHMAP_SIZE, ia);
    *reinterpret_cast<float4*>(srow + 4 * 4) = blend8(B, wb);
    level_idx<2>(cx, cy, cz, ib, wb); load8(B, tb + 2u * HASHMAP_SIZE, ib);
    *reinterpret_cast<float4*>(srow + 3 * 4) = blend8(A, wa);
    level_idx<1>(cx, cy, cz, ia, wa); load8(A, tb + 1u * HASHMAP_SIZE, ia);
    *reinterpret_cast<float4*>(srow + 2 * 4) = blend8(B, wb);
    level_idx<0>(cx, cy, cz, ib, wb); load8(B, tb, ib);
    *reinterpret_cast<float4*>(srow + 1 * 4) = blend8(A, wa);
    *reinterpret_cast<float4*>(srow + 0 * 4) = blend8(B, wb);

    __syncwarp();

    const unsigned fullmask = 0xffffffffu;
    unsigned m = __ballot_sync(fullmask, active);
    bool warp_full = (m == 0xffffffffu);

    if (warp_full) {
#pragma unroll
        for (int it = 0; it < 7; ++it) {
            int f  = it * 30 + lane;
            int fc = f < 192 ? f : 191;
            int r  = fc / 6;
            int L  = fc - r * 6;
            float4 v = *reinterpret_cast<float4*>(&sbuf[w][r][L * 4]);
            uint32_t org_r = __shfl_sync(fullmask, orig, r);
            if (lane < 30 && f < 192)
                stcs_f4(&out[(size_t)org_r * 6 + L], v);
        }
    } else if (active) {
        float4* orow = out + (size_t)orig * 6;
#pragma unroll
        for (int L = 0; L < N_LEVELS; ++L)
            stcs_f4(&orow[L], *reinterpret_cast<float4*>(srow + L * 4));
    }
}

// ---------------------------------------------------------------- fused launch wrappers
__global__ void __launch_bounds__(256)
f1_histA(const float* __restrict__ dirs, const float* __restrict__ origs, int nA)
{
    dev_hist(dirs, origs, 0, nA, reinterpret_cast<uint32_t*>(d_hist0), blockIdx.x);
}

__global__ void __launch_bounds__(256)
f2_scanA_histB(const float* __restrict__ dirs, const float* __restrict__ origs, int nA, int nB)
{
    if (blockIdx.x < SCAN_BLOCKS)
        dev_scan(reinterpret_cast<uint32_t*>(d_hist0), reinterpret_cast<uint32_t*>(d_off0),
                 d_bsum0, blockIdx.x);
    else
        dev_hist(dirs, origs, nA, nB, reinterpret_cast<uint32_t*>(d_hist1),
                 blockIdx.x - SCAN_BLOCKS);
}

__global__ void __launch_bounds__(256)
f3_scanB_scatA(const float* __restrict__ dirs, const float* __restrict__ origs, int nA, int nB)
{
    if (blockIdx.x < SCAN_BLOCKS)
        dev_scan(reinterpret_cast<uint32_t*>(d_hist1), reinterpret_cast<uint32_t*>(d_off1),
                 d_bsum1, blockIdx.x);
    else
        dev_scatter(dirs, origs, 0, nA, reinterpret_cast<uint32_t*>(d_off0), d_bsum0,
                    0u, blockIdx.x - SCAN_BLOCKS);
}

__global__ void __launch_bounds__(256)
f4_encA_scatB(const float* __restrict__ table, float4* __restrict__ out,
              const float* __restrict__ dirs, const float* __restrict__ origs,
              int nA, int nB, int bA)
{
    if ((int)blockIdx.x < bA)
        dev_encode(table, out, 0u, nA, blockIdx.x);
    else
        dev_scatter(dirs, origs, nA, nB, reinterpret_cast<uint32_t*>(d_off1), d_bsum1,
                    (uint32_t)nA, blockIdx.x - bA);
}

__global__ void __launch_bounds__(256)
f5_encB(const float* __restrict__ table, float4* __restrict__ out, int nA, int nB)
{
    dev_encode(table, out, (uint32_t)nA, nB, blockIdx.x);
}

// ---------------------------------------------------------------- launch
extern "C" void kernel_launch(void* const* d_in, const int* in_sizes, int n_in,
                              void* d_out, int out_size)
{
    const float* view_dirs   = (const float*)d_in[0];
    const float* ray_origins = (const float*)d_in[1];
    const float* table       = (const float*)d_in[2];
    float4* out              = (float4*)d_out;

    int n  = in_sizes[0] / 3;
    int nA = (n + 1) / 2;
    int nB = n - nA;
    int bA = (nA + 255) / 256;
    int bB = (nB + 255) / 256;

    f1_histA<<<bA, 256>>>(view_dirs, ray_origins, nA);
    f2_scanA_histB<<<SCAN_BLOCKS + bB, 256>>>(view_dirs, ray_origins, nA, nB);
    f3_scanB_scatA<<<SCAN_BLOCKS + bA, 256>>>(view_dirs, ray_origins, nA, nB);
    f4_encA_scatB<<<bA + bB, 256>>>(table, out, view_dirs, ray_origins, nA, nB, bA);
    f5_encB<<<bB, 256>>>(table, out, nA, nB);
}